// round 2
// baseline (speedup 1.0000x reference)
#include <cuda_runtime.h>
#include <cstdint>

#define BB      8
#define CTOT    256
#define HH      96
#define WW      128
#define TH      2                 // output rows per block
#define ROWT    (HH/TH)           // 48 row-tiles
#define CCK     4                 // channels per chunk (halved for 2 blocks/SM)
#define NCHUNK  (CTOT/CCK)        // 64
#define THREADS 288               // 9 warps (one per dy)

#define S2_ROWSTRIDE 640                       // bytes, mult of 128 (halo 136 floats used)
#define S2_CSTRIDE   (10*S2_ROWSTRIDE)         // 6400
#define S1_ROWSTRIDE 512                       // 128 floats
#define S1_CSTRIDE   (2*S1_ROWSTRIDE)          // 1024
#define S1_BYTES     (CCK*S1_CSTRIDE)          // 4096
#define S2_BYTES     (CCK*S2_CSTRIDE)          // 25600
#define BUF_BYTES    (S1_BYTES + S2_BYTES)     // 29696
#define SMEM_TOTAL   (2*BUF_BYTES)             // 59392 -> 2 blocks/SM

typedef unsigned long long ull;

__device__ __forceinline__ uint32_t swz(uint32_t u) { return u ^ ((u >> 3) & 0x70u); }

__device__ __forceinline__ float4 lds128(uint32_t addr) {
    float4 v;
    asm volatile("ld.shared.v4.f32 {%0,%1,%2,%3}, [%4];"
                 : "=f"(v.x), "=f"(v.y), "=f"(v.z), "=f"(v.w) : "r"(addr));
    return v;
}
__device__ __forceinline__ void sts_zero16(uint32_t addr) {
    asm volatile("st.shared.v4.b32 [%0], {%1,%1,%1,%1};" :: "r"(addr), "r"(0) : "memory");
}
__device__ __forceinline__ void cpa16(uint32_t dst, const float* src) {
    asm volatile("cp.async.cg.shared.global [%0], [%1], 16;" :: "r"(dst), "l"(src));
}
__device__ __forceinline__ ull pk(float lo, float hi) {
    ull r;
    asm("mov.b64 %0, {%1,%2};" : "=l"(r) : "f"(lo), "f"(hi));
    return r;
}
__device__ __forceinline__ float2 upk(ull v) {
    float2 f;
    asm("mov.b64 {%0,%1}, %2;" : "=f"(f.x), "=f"(f.y) : "l"(v));
    return f;
}
__device__ __forceinline__ void ffma2(ull& d, ull a, ull b) {
    asm("fma.rn.f32x2 %0, %1, %2, %0;" : "+l"(d) : "l"(a), "l"(b));
}

__device__ __forceinline__ void load_chunk(uint32_t bufbase,
                                           const float* __restrict__ in1,
                                           const float* __restrict__ in2,
                                           int b, int c0, int h0, int tid)
{
    const uint32_t s2b = bufbase + S1_BYTES;
    // in2 halo: CCK chans x 10 rows x 32 interior 16B chunks (pads pre-zeroed)
    for (int idx = tid; idx < CCK * 10 * 32; idx += THREADS) {
        int row = idx >> 5;
        int ch  = (idx & 31) + 1;           // interior chunk 1..32
        int c   = row / 10;
        int rr  = row - c * 10;
        int hh  = h0 - 4 + rr;
        if (hh >= 0 && hh < HH) {
            const float* src = in2 + ((((b * CTOT) + c0 + c) * HH + hh) * WW) + (ch - 1) * 4;
            cpa16(s2b + c * S2_CSTRIDE + rr * S2_ROWSTRIDE + swz((uint32_t)(ch * 16)), src);
        }
    }
    // in1: CCK chans x 2 rows x 32 chunks
    for (int idx = tid; idx < CCK * 2 * 32; idx += THREADS) {
        int row = idx >> 5;
        int ch  = idx & 31;
        int c   = row >> 1;
        int rr  = row & 1;
        const float* src = in1 + ((((b * CTOT) + c0 + c) * HH + h0 + rr) * WW) + ch * 4;
        cpa16(bufbase + c * S1_CSTRIDE + rr * S1_ROWSTRIDE + swz((uint32_t)(ch * 16)), src);
    }
    asm volatile("cp.async.commit_group;" ::: "memory");
}

__device__ __forceinline__ void compute_chunk(uint32_t bufbase,
                                              const uint32_t offA0, const uint32_t offA1,
                                              const uint32_t* offR, ull acc[9][4])
{
#pragma unroll
    for (int cc = 0; cc < CCK; cc++) {
        const uint32_t a1b = bufbase + cc * S1_CSTRIDE;
        float4 qa0 = lds128(a1b + offA0);
        float4 qa1 = lds128(a1b + offA1);
        const uint32_t s2b = bufbase + S1_BYTES + cc * S2_CSTRIDE;
        float4 q0 = lds128(s2b + offR[0]);
        float4 q1 = lds128(s2b + offR[1]);
        float4 q2 = lds128(s2b + offR[2]);
        float4 q3 = lds128(s2b + offR[3]);

        ull A[4];
        A[0] = pk(qa0.x, qa0.y); A[1] = pk(qa0.z, qa0.w);
        A[2] = pk(qa1.x, qa1.y); A[3] = pk(qa1.z, qa1.w);

        float rv[16] = { q0.x, q0.y, q0.z, q0.w,  q1.x, q1.y, q1.z, q1.w,
                         q2.x, q2.y, q2.z, q2.w,  q3.x, q3.y, q3.z, q3.w };
        ull E[8], O[7];
#pragma unroll
        for (int j = 0; j < 8; j++) E[j] = pk(rv[2 * j], rv[2 * j + 1]);
#pragma unroll
        for (int j = 0; j < 7; j++) O[j] = pk(rv[2 * j + 1], rv[2 * j + 2]);

#pragma unroll
        for (int d = 0; d < 9; d++) {
#pragma unroll
            for (int p = 0; p < 4; p++) {
                ull bo = (d & 1) ? O[p + (d >> 1)] : E[p + (d >> 1)];
                ffma2(acc[d][p], A[p], bo);
            }
        }
    }
}

__global__ void __launch_bounds__(THREADS, 2)
corr_kernel(const float* __restrict__ in1, const float* __restrict__ in2,
            float* __restrict__ out)
{
    extern __shared__ char smem[];
    const uint32_t smem32 = (uint32_t)__cvta_generic_to_shared(smem);

    const int tid  = threadIdx.x;
    const int warp = tid >> 5;        // dy index 0..8
    const int lane = tid & 31;
    const int r    = lane >> 4;       // output row within tile, 0..1
    const int g    = lane & 15;       // w-group (8 pixels each)
    const int w0   = g << 3;

    const int bx = blockIdx.x;
    const int b  = bx / ROWT;
    const int h0 = (bx - b * ROWT) * TH;

    // Per-thread read offsets (swizzled, channel-invariant)
    const uint32_t offA0 = (uint32_t)(r * S1_ROWSTRIDE) + swz((uint32_t)(32 * g));
    const uint32_t offA1 = (uint32_t)(r * S1_ROWSTRIDE) + swz((uint32_t)(32 * g + 16));
    uint32_t offR[4];
#pragma unroll
    for (int j = 0; j < 4; j++)
        offR[j] = (uint32_t)((r + warp) * S2_ROWSTRIDE) + swz((uint32_t)(32 * g + 16 * j));

    // Pre-zero pad regions of both buffers (left/right halo chunks + OOB rows).
    for (int idx = tid; idx < 2 * CCK * 10; idx += THREADS) {
        int buf = idx / (CCK * 10);
        int rem = idx - buf * (CCK * 10);
        int c = rem / 10, rr = rem - c * 10;
        int hh = h0 - 4 + rr;
        uint32_t rowaddr = smem32 + buf * BUF_BYTES + S1_BYTES + c * S2_CSTRIDE + rr * S2_ROWSTRIDE;
        sts_zero16(rowaddr + swz(0u));
        sts_zero16(rowaddr + swz(33u * 16u));
        if (hh < 0 || hh >= HH) {
            for (int ch = 1; ch < 33; ch++) sts_zero16(rowaddr + swz((uint32_t)(ch * 16)));
        }
    }

    ull acc[9][4];
#pragma unroll
    for (int d = 0; d < 9; d++)
#pragma unroll
        for (int p = 0; p < 4; p++) acc[d][p] = 0ull;

    load_chunk(smem32, in1, in2, b, 0, h0, tid);

    for (int k = 0; k < NCHUNK; k++) {
        if (k + 1 < NCHUNK) {
            load_chunk(smem32 + (uint32_t)(((k + 1) & 1) * BUF_BYTES), in1, in2,
                       b, (k + 1) * CCK, h0, tid);
            asm volatile("cp.async.wait_group 1;" ::: "memory");
        } else {
            asm volatile("cp.async.wait_group 0;" ::: "memory");
        }
        __syncthreads();
        compute_chunk(smem32 + (uint32_t)((k & 1) * BUF_BYTES), offA0, offA1, offR, acc);
        __syncthreads();
    }

    // Epilogue: out[b, warp*9+d, h0+r, w0..w0+7] = acc / 256
    const float inv = 1.0f / 256.0f;
    const int hOut = h0 + r;
#pragma unroll
    for (int d = 0; d < 9; d++) {
        int n = warp * 9 + d;
        float* op = out + ((size_t)((b * 81 + n) * HH + hOut)) * WW + w0;
        float2 u0 = upk(acc[d][0]);
        float2 u1 = upk(acc[d][1]);
        float2 u2 = upk(acc[d][2]);
        float2 u3 = upk(acc[d][3]);
        float4 v0 = make_float4(u0.x * inv, u0.y * inv, u1.x * inv, u1.y * inv);
        float4 v1 = make_float4(u2.x * inv, u2.y * inv, u3.x * inv, u3.y * inv);
        *(float4*)op       = v0;
        *(float4*)(op + 4) = v1;
    }
}

extern "C" void kernel_launch(void* const* d_in, const int* in_sizes, int n_in,
                              void* d_out, int out_size)
{
    const float* in1 = (const float*)d_in[0];
    const float* in2 = (const float*)d_in[1];
    float* out = (float*)d_out;

    cudaFuncSetAttribute(corr_kernel, cudaFuncAttributeMaxDynamicSharedMemorySize, SMEM_TOTAL);
    corr_kernel<<<BB * ROWT, THREADS, SMEM_TOTAL>>>(in1, in2, out);
}

// round 3
// speedup vs baseline: 1.3196x; 1.3196x over previous
#include <cuda_runtime.h>
#include <cstdint>

#define BB      8
#define CTOT    256
#define HH      96
#define WW      128
#define ROWT    HH                // TH=1: one output row per block
#define CCK     8                 // channels per chunk
#define NCHUNK  (CTOT/CCK)        // 32
#define THREADS 288               // 9 warps (one per dy)

#define S2_ROWSTRIDE 640                       // bytes (136 floats used), mult of 128
#define S2_CSTRIDE   (9*S2_ROWSTRIDE)          // 9 halo rows per channel = 5760
#define S1_ROWSTRIDE 512                       // 128 floats
#define S1_CSTRIDE   S1_ROWSTRIDE              // 1 row per channel
#define S1_BYTES     (CCK*S1_CSTRIDE)          // 4096
#define S2_BYTES     (CCK*S2_CSTRIDE)          // 46080
#define BUF_BYTES    (S1_BYTES + S2_BYTES)     // 50176
#define SMEM_TOTAL   (2*BUF_BYTES)             // 100352 -> 2 blocks/SM

typedef unsigned long long ull;

__device__ __forceinline__ float4 lds128(uint32_t addr) {
    float4 v;
    asm volatile("ld.shared.v4.f32 {%0,%1,%2,%3}, [%4];"
                 : "=f"(v.x), "=f"(v.y), "=f"(v.z), "=f"(v.w) : "r"(addr));
    return v;
}
__device__ __forceinline__ void sts_zero16(uint32_t addr) {
    asm volatile("st.shared.v4.b32 [%0], {%1,%1,%1,%1};" :: "r"(addr), "r"(0) : "memory");
}
__device__ __forceinline__ void cpa16(uint32_t dst, const float* src) {
    asm volatile("cp.async.cg.shared.global [%0], [%1], 16;" :: "r"(dst), "l"(src));
}
__device__ __forceinline__ ull pk(float lo, float hi) {
    ull r;
    asm("mov.b64 %0, {%1,%2};" : "=l"(r) : "f"(lo), "f"(hi));
    return r;
}
__device__ __forceinline__ float2 upk(ull v) {
    float2 f;
    asm("mov.b64 {%0,%1}, %2;" : "=f"(f.x), "=f"(f.y) : "l"(v));
    return f;
}
__device__ __forceinline__ void ffma2(ull& d, ull a, ull b) {
    asm("fma.rn.f32x2 %0, %1, %2, %0;" : "+l"(d) : "l"(a), "l"(b));
}

__device__ __forceinline__ void load_chunk(uint32_t bufbase,
                                           const float* __restrict__ in1,
                                           const float* __restrict__ in2,
                                           int b, int c0, int h0, int tid)
{
    const uint32_t s2b = bufbase + S1_BYTES;
    // in2 halo: CCK chans x 9 rows x 32 interior 16B chunks (pads pre-zeroed)
    for (int idx = tid; idx < CCK * 9 * 32; idx += THREADS) {
        int row = idx >> 5;
        int ch  = (idx & 31) + 1;           // interior chunk 1..32
        int c   = row / 9;
        int rr  = row - c * 9;
        int hh  = h0 - 4 + rr;
        if (hh >= 0 && hh < HH) {
            const float* src = in2 + ((((b * CTOT) + c0 + c) * HH + hh) * WW) + (ch - 1) * 4;
            cpa16(s2b + c * S2_CSTRIDE + rr * S2_ROWSTRIDE + (uint32_t)(ch * 16), src);
        }
    }
    // in1: CCK chans x 1 row x 32 chunks
    for (int idx = tid; idx < CCK * 32; idx += THREADS) {
        int c   = idx >> 5;
        int ch  = idx & 31;
        const float* src = in1 + ((((b * CTOT) + c0 + c) * HH + h0) * WW) + ch * 4;
        cpa16(bufbase + c * S1_CSTRIDE + (uint32_t)(ch * 16), src);
    }
    asm volatile("cp.async.commit_group;" ::: "memory");
}

__device__ __forceinline__ void compute_chunk(uint32_t bufbase,
                                              const uint32_t offA,
                                              const uint32_t* offB, ull acc[9][2])
{
#pragma unroll
    for (int cc = 0; cc < CCK; cc++) {
        float4 qa = lds128(bufbase + cc * S1_CSTRIDE + offA);
        const uint32_t s2b = bufbase + S1_BYTES + cc * S2_CSTRIDE;
        float4 q0 = lds128(s2b + offB[0]);
        float4 q1 = lds128(s2b + offB[1]);
        float4 q2 = lds128(s2b + offB[2]);

        ull A0 = pk(qa.x, qa.y);
        ull A1 = pk(qa.z, qa.w);

        float rv[12] = { q0.x, q0.y, q0.z, q0.w,
                         q1.x, q1.y, q1.z, q1.w,
                         q2.x, q2.y, q2.z, q2.w };
        ull E[6], O[5];
#pragma unroll
        for (int j = 0; j < 6; j++) E[j] = pk(rv[2 * j], rv[2 * j + 1]);
#pragma unroll
        for (int j = 0; j < 5; j++) O[j] = pk(rv[2 * j + 1], rv[2 * j + 2]);

#pragma unroll
        for (int d = 0; d < 9; d++) {
            ull b0 = (d & 1) ? O[(d >> 1)]     : E[(d >> 1)];
            ull b1 = (d & 1) ? O[(d >> 1) + 1] : E[(d >> 1) + 1];
            ffma2(acc[d][0], A0, b0);
            ffma2(acc[d][1], A1, b1);
        }
    }
}

__global__ void __launch_bounds__(THREADS, 2)
corr_kernel(const float* __restrict__ in1, const float* __restrict__ in2,
            float* __restrict__ out)
{
    extern __shared__ char smem[];
    const uint32_t smem32 = (uint32_t)__cvta_generic_to_shared(smem);

    const int tid  = threadIdx.x;
    const int warp = tid >> 5;        // dy index 0..8
    const int g    = tid & 31;        // w-group (4 pixels each)
    const int w0   = g << 2;

    const int bx = blockIdx.x;
    const int b  = bx / ROWT;
    const int h0 = bx - b * ROWT;     // output row

    // Per-thread read offsets (no swizzle: all accesses warp-contiguous)
    const uint32_t offA = (uint32_t)(16 * g);
    uint32_t offB[3];
#pragma unroll
    for (int j = 0; j < 3; j++)
        offB[j] = (uint32_t)(warp * S2_ROWSTRIDE + 16 * g + 16 * j);

    // Pre-zero pad regions of both buffers (left/right halo chunks + OOB rows).
    for (int idx = tid; idx < 2 * CCK * 9; idx += THREADS) {
        int buf = idx / (CCK * 9);
        int rem = idx - buf * (CCK * 9);
        int c = rem / 9, rr = rem - c * 9;
        int hh = h0 - 4 + rr;
        uint32_t rowaddr = smem32 + buf * BUF_BYTES + S1_BYTES + c * S2_CSTRIDE + rr * S2_ROWSTRIDE;
        sts_zero16(rowaddr);                       // left pad (floats -4..-1)
        sts_zero16(rowaddr + 33u * 16u);           // right pad (floats 128..131)
        if (hh < 0 || hh >= HH) {
            for (int ch = 1; ch < 33; ch++) sts_zero16(rowaddr + (uint32_t)(ch * 16));
        }
    }

    ull acc[9][2];
#pragma unroll
    for (int d = 0; d < 9; d++) { acc[d][0] = 0ull; acc[d][1] = 0ull; }

    load_chunk(smem32, in1, in2, b, 0, h0, tid);

    for (int k = 0; k < NCHUNK; k++) {
        if (k + 1 < NCHUNK) {
            load_chunk(smem32 + (uint32_t)(((k + 1) & 1) * BUF_BYTES), in1, in2,
                       b, (k + 1) * CCK, h0, tid);
            asm volatile("cp.async.wait_group 1;" ::: "memory");
        } else {
            asm volatile("cp.async.wait_group 0;" ::: "memory");
        }
        __syncthreads();
        compute_chunk(smem32 + (uint32_t)((k & 1) * BUF_BYTES), offA, offB, acc);
        __syncthreads();
    }

    // Epilogue: out[b, warp*9+d, h0, w0..w0+3] = acc / 256
    const float inv = 1.0f / 256.0f;
#pragma unroll
    for (int d = 0; d < 9; d++) {
        int n = warp * 9 + d;
        float* op = out + ((size_t)((b * 81 + n) * HH + h0)) * WW + w0;
        float2 u0 = upk(acc[d][0]);
        float2 u1 = upk(acc[d][1]);
        *(float4*)op = make_float4(u0.x * inv, u0.y * inv, u1.x * inv, u1.y * inv);
    }
}

extern "C" void kernel_launch(void* const* d_in, const int* in_sizes, int n_in,
                              void* d_out, int out_size)
{
    const float* in1 = (const float*)d_in[0];
    const float* in2 = (const float*)d_in[1];
    float* out = (float*)d_out;

    cudaFuncSetAttribute(corr_kernel, cudaFuncAttributeMaxDynamicSharedMemorySize, SMEM_TOTAL);
    corr_kernel<<<BB * ROWT, THREADS, SMEM_TOTAL>>>(in1, in2, out);
}